// round 15
// baseline (speedup 1.0000x reference)
#include <cuda_runtime.h>

// DetectionLoss, fused single-kernel, round 15 resubmit of round-14 (sm_103a).
// pred: (B=32, C=24, H=160, W=160) fp32; targets: (N<=512, 6) fp32; out: 1 fp32.
//
// Round-14 changes vs round-13 (11.0us, DRAM 12.9%, occ 48.7%):
//  1. FORCED load batching: 4x asm volatile ld.global.nc.v4 with precomputed
//     pointers -> guaranteed back-to-back LDG.E.128 in SASS (MLP_p1=4).
//     (Two previous rounds asked politely; ptxas interleaved at regs=28.)
//  2. __threadfence() + completion atomic moved to thread 0 ONLY (was all
//     165,888 threads executing membar.gl -> suspected geometry-invariant
//     serial floor). Shared is_last broadcast + extra __syncthreads removed.

#define HW        25600          // 160*160
#define GW        160
#define GH        160
#define NCLS      3
#define TOT_CONF  (32 * 3 * HW)  // 2,457,600 elements; 614,400 float4
#define CONF_BLOCKS 600
#define NTHREADS  256
// f4-index: i = i0 + k*153600, i0 in [0,153600); plane = i/6400 = plane0+24k
//   f4 address = plane*51200 + 25600 + (i0 % 6400); k-stride = 24*51200 f4
#define PLANE_F4  51200          // 8*HW/4
#define CONF_F4   25600          // 4*HW/4
#define KSTRIDE_F4 (24 * PLANE_F4)

// [0]=conf sum(s^2), [1]=box, [2]=cls, [3]=conf corr, [4]=valid count
__device__ double g_acc[8];
__device__ unsigned int g_done;   // zero at module load; reset by finalizer

__device__ __forceinline__ float tanh_ap(float x) {
    float y;
    asm("tanh.approx.f32 %0, %1;" : "=f"(y) : "f"(x));
    return y;
}
__device__ __forceinline__ float sig1(float x) {        // 1 MUFU
    return 0.5f * tanh_ap(0.5f * x) + 0.5f;
}
__device__ __forceinline__ float sig_precise(float x) { // sparse part
    return __fdividef(1.0f, 1.0f + __expf(-x));
}

// Volatile vector load: cannot be reordered against other volatile asms ->
// four consecutive calls emit four back-to-back LDG.E.128.
__device__ __forceinline__ float4 ldg_v4(const float4* p) {
    float4 v;
    asm volatile("ld.global.nc.v4.f32 {%0,%1,%2,%3}, [%4];"
                 : "=f"(v.x), "=f"(v.y), "=f"(v.z), "=f"(v.w) : "l"(p));
    return v;
}

// Block sum: fp32 within warp, double across warps. Valid on tid 0. 256 thr.
__device__ __forceinline__ double blk_sum_f(float v) {
    __shared__ double sh[8];
#pragma unroll
    for (int o = 16; o > 0; o >>= 1) v += __shfl_down_sync(0xffffffffu, v, o);
    const int lane = threadIdx.x & 31, w = threadIdx.x >> 5;
    if (lane == 0) sh[w] = (double)v;
    __syncthreads();
    double d = 0.0;
    if (w == 0) {
        d = (lane < 8) ? sh[lane] : 0.0;
#pragma unroll
        for (int o = 4; o > 0; o >>= 1) d += __shfl_down_sync(0xffffffffu, d, o);
    }
    __syncthreads();
    return d;
}

__device__ __forceinline__ void epilogue(unsigned int grid, float* out) {
    // thread 0 only: order my atomics before the completion count, then
    // the last-arriving block finalizes and resets for the next graph replay.
    __threadfence();
    const unsigned int done = atomicAdd(&g_done, 1u) + 1u;
    if (done == grid) {
        __threadfence();
        volatile double* a = g_acc;
        const double nobj = 3.0 * a[4];
        const double loss = 5.0 * a[1] / (nobj * 4.0)
                          + (a[0] + a[3]) / (double)TOT_CONF
                          + a[2] / (nobj * (double)NCLS);
        out[0] = (float)loss;
        a[0] = 0.0; a[1] = 0.0; a[2] = 0.0; a[3] = 0.0; a[4] = 0.0;
        g_done = 0u;
    }
}

__global__ void __launch_bounds__(NTHREADS, 4)
fused_loss_kernel(const float* __restrict__ pred,
                  const float* __restrict__ tg,
                  int N,
                  float* __restrict__ out) {
    const int bid = blockIdx.x;

    if (bid < CONF_BLOCKS) {
        // ---- dense conf: 4 forced-batched LDG.128 ----
        const int i0     = bid * NTHREADS + threadIdx.x;   // [0, 153600)
        const int plane0 = i0 / 6400;
        const int hw4    = i0 - plane0 * 6400;
        const float4* p0 = reinterpret_cast<const float4*>(pred)
                         + (size_t)plane0 * PLANE_F4 + CONF_F4 + hw4;
        const float4* p1 = p0 + KSTRIDE_F4;
        const float4* p2 = p1 + KSTRIDE_F4;
        const float4* p3 = p2 + KSTRIDE_F4;
        const float4 v0 = ldg_v4(p0);
        const float4 v1 = ldg_v4(p1);
        const float4 v2 = ldg_v4(p2);
        const float4 v3 = ldg_v4(p3);

        float acc = 0.0f;
        {
            float s;
            s = sig1(v0.x); acc += s * s;  s = sig1(v0.y); acc += s * s;
            s = sig1(v0.z); acc += s * s;  s = sig1(v0.w); acc += s * s;
            s = sig1(v1.x); acc += s * s;  s = sig1(v1.y); acc += s * s;
            s = sig1(v1.z); acc += s * s;  s = sig1(v1.w); acc += s * s;
            s = sig1(v2.x); acc += s * s;  s = sig1(v2.y); acc += s * s;
            s = sig1(v2.z); acc += s * s;  s = sig1(v2.w); acc += s * s;
            s = sig1(v3.x); acc += s * s;  s = sig1(v3.y); acc += s * s;
            s = sig1(v3.z); acc += s * s;  s = sig1(v3.w); acc += s * s;
        }
        const double tot = blk_sum_f(acc);
        if (threadIdx.x == 0) {
            atomicAdd(&g_acc[0], tot);
            epilogue(gridDim.x, out);
        }
    } else {
        // ---- sparse targets: 1 thread per (n, anchor, channel) ----
        const int t = (bid - CONF_BLOCKS) * NTHREADS + threadIdx.x;
        float vb = 0.0f, vc = 0.0f, vr = 0.0f, vn = 0.0f;
        if (t < N * 24) {
            const int n  = t / 24;
            const int r  = t - n * 24;
            const int a  = r >> 3;
            const int ch = r & 7;
            const float* T = tg + n * 6;
            const int b  = (int)T[0];
            const int c  = (int)T[1];
            const int gx = (int)(T[2] * (float)GW);
            const int gy = (int)(T[3] * (float)GH);
            if (gx >= 0 && gx < GW && gy >= 0 && gy < GH) {
                const float p = pred[(size_t)(b * 24 + a * 8 + ch) * HW + gy * GW + gx];
                const float s = sig_precise(p);
                if (ch < 4) {
                    const float q = (ch < 2) ? s : __expf(p);
                    const float d = q - T[2 + ch];
                    vb = d * d;
                } else if (ch == 4) {
                    vr = 1.0f - 2.0f * s;             // (s-1)^2 - s^2
                } else {
                    const float oh = (c == ch - 5) ? 1.0f : 0.0f;
                    const float d  = s - oh;
                    vc = d * d;
                }
                if (r == 0) vn = 1.0f;
            }
        }
        const double rb = blk_sum_f(vb);
        const double rc = blk_sum_f(vc);
        const double rr = blk_sum_f(vr);
        const double rv = blk_sum_f(vn);
        if (threadIdx.x == 0) {
            atomicAdd(&g_acc[1], rb);
            atomicAdd(&g_acc[2], rc);
            atomicAdd(&g_acc[3], rr);
            atomicAdd(&g_acc[4], rv);
            epilogue(gridDim.x, out);
        }
    }
}

extern "C" void kernel_launch(void* const* d_in, const int* in_sizes, int n_in,
                              void* d_out, int out_size) {
    const float* pred = (const float*)d_in[0];
    const float* tg   = (const float*)d_in[1];
    const int N = in_sizes[1] / 6;
    const int tgt_blocks = (N * 24 + NTHREADS - 1) / NTHREADS;
    fused_loss_kernel<<<CONF_BLOCKS + tgt_blocks, NTHREADS>>>(pred, tg, N, (float*)d_out);
}